// round 6
// baseline (speedup 1.0000x reference)
#include <cuda_runtime.h>
#include <math.h>

#define NUM_USERS 100000
#define NUM_ITEMS 50000
#define N_NODES   (NUM_USERS + NUM_ITEMS)   // 150000
#define LATENT    64
#define N_EDGES   2400000
#define BATCH     16384

// ---------------------------------------------------------------------------
// Scratch (device globals: allocation-free, graph-capture safe, ~135 MB)
// ---------------------------------------------------------------------------
__device__ float g_L1[N_NODES * LATENT];     // layer outputs, 38.4 MB each
__device__ float g_L2[N_NODES * LATENT];
__device__ float g_L3[N_NODES * LATENT];
__device__ int   g_counts[N_NODES];          // per-row edge counts
__device__ int   g_row_ptr[N_NODES + 1];     // CSR offsets
__device__ int   g_fill[N_NODES];            // scatter cursors
__device__ int2  g_ecv[N_EDGES];             // packed (col, val) sorted by row

// ---------------------------------------------------------------------------
// CSR build step 1: zero the histogram
// ---------------------------------------------------------------------------
__global__ void zero_counts_kernel()
{
    int i = blockIdx.x * blockDim.x + threadIdx.x;
    if (i < N_NODES) g_counts[i] = 0;
}

// step 2: histogram of destination rows
__global__ void hist_kernel(const int* __restrict__ rows)
{
    int i = blockIdx.x * blockDim.x + threadIdx.x;
    if (i < N_EDGES) atomicAdd(&g_counts[rows[i]], 1);
}

// step 3: exclusive scan (single block, 1024 threads, serial chunks + block scan)
#define SCAN_T   1024
#define SCAN_CHK ((N_NODES + SCAN_T - 1) / SCAN_T)   // 147
__global__ void scan_kernel()
{
    __shared__ int ssum[SCAN_T];
    int t = threadIdx.x;
    int begin = t * SCAN_CHK;
    int end   = min(begin + SCAN_CHK, N_NODES);

    int s = 0;
    for (int i = begin; i < end; i++) s += g_counts[i];
    ssum[t] = s;
    __syncthreads();

    // Hillis-Steele inclusive scan over 1024 partials
    for (int d = 1; d < SCAN_T; d <<= 1) {
        int v = (t >= d) ? ssum[t - d] : 0;
        __syncthreads();
        ssum[t] += v;
        __syncthreads();
    }

    int run = (t == 0) ? 0 : ssum[t - 1];
    for (int i = begin; i < end; i++) {
        g_row_ptr[i] = run;
        g_fill[i]    = run;
        run += g_counts[i];
    }
    if (t == SCAN_T - 1) g_row_ptr[N_NODES] = ssum[SCAN_T - 1];
}

// step 4: scatter packed (col, val) pairs into row-sorted order
__global__ void scatter_kernel(const int*   __restrict__ rows,
                               const int*   __restrict__ cols,
                               const float* __restrict__ vals)
{
    int i = blockIdx.x * blockDim.x + threadIdx.x;
    if (i >= N_EDGES) return;
    int r   = rows[i];
    int pos = atomicAdd(&g_fill[r], 1);
    g_ecv[pos] = make_int2(cols[i], __float_as_int(vals[i]));
}

// ---------------------------------------------------------------------------
// CSR SPMM: one warp per output row. Edges of the row are contiguous; the
// warp accumulates its 64-dim output in registers (lane owns dims {lane,
// lane+32}) and writes it once. No atomics, no destination pre-zeroing.
// (col,val) loads are warp-broadcast; gathers are 128B coalesced; unroll-4
// gives 8 independent in-flight gathers to hide L2-hit latency.
// mode 0: split input embeddings -> L1 ; 1: L1 -> L2 ; 2: L2 -> L3
// ---------------------------------------------------------------------------
__global__ void spmm_csr(const float* __restrict__ uemb,
                         const float* __restrict__ iemb,
                         int mode)
{
    int gwarp = (blockIdx.x * blockDim.x + threadIdx.x) >> 5;
    if (gwarp >= N_NODES) return;
    int lane = threadIdx.x & 31;

    const float* __restrict__ xs =
        (mode == 1) ? g_L1 : (mode == 2) ? g_L2 : (const float*)0;
    float* __restrict__ dst =
        (mode == 0) ? g_L1 : (mode == 1) ? g_L2 : g_L3;

    int start = g_row_ptr[gwarp];
    int end   = g_row_ptr[gwarp + 1];

    float a0 = 0.f, a1 = 0.f;

    #define XROW(cc) ((mode == 0)                                            \
        ? (((cc) < NUM_USERS) ? uemb + (cc) * LATENT                         \
                              : iemb + ((cc) - NUM_USERS) * LATENT)          \
        : xs + (cc) * LATENT)

    int e = start;
    for (; e + 4 <= end; e += 4) {
        int2 cv0 = g_ecv[e],     cv1 = g_ecv[e + 1],
             cv2 = g_ecv[e + 2], cv3 = g_ecv[e + 3];
        const float* x0 = XROW(cv0.x);
        const float* x1 = XROW(cv1.x);
        const float* x2 = XROW(cv2.x);
        const float* x3 = XROW(cv3.x);
        float p0a = x0[lane], p0b = x0[lane + 32];
        float p1a = x1[lane], p1b = x1[lane + 32];
        float p2a = x2[lane], p2b = x2[lane + 32];
        float p3a = x3[lane], p3b = x3[lane + 32];
        float v0 = __int_as_float(cv0.y), v1 = __int_as_float(cv1.y);
        float v2 = __int_as_float(cv2.y), v3 = __int_as_float(cv3.y);
        a0 = fmaf(v0, p0a, a0);  a1 = fmaf(v0, p0b, a1);
        a0 = fmaf(v1, p1a, a0);  a1 = fmaf(v1, p1b, a1);
        a0 = fmaf(v2, p2a, a0);  a1 = fmaf(v2, p2b, a1);
        a0 = fmaf(v3, p3a, a0);  a1 = fmaf(v3, p3b, a1);
    }
    for (; e < end; e++) {
        int2 cv = g_ecv[e];
        const float* x = XROW(cv.x);
        float v = __int_as_float(cv.y);
        a0 = fmaf(v, x[lane],      a0);
        a1 = fmaf(v, x[lane + 32], a1);
    }

    dst[gwarp * LATENT + lane]      = a0;
    dst[gwarp * LATENT + lane + 32] = a1;
    #undef XROW
}

// ---------------------------------------------------------------------------
// MLP head: one warp per sample.
//   v  = 0.25 * concat(sum_row(user), sum_row(item))        (128)
//        where sum_row(n) = emb[n] + L1[n] + L2[n] + L3[n]
//   h0 = relu(v @ W0 + b0); h1 = relu(h0 @ W1 + b1)
//   out = sigmoid(h1 @ Wa + ba)
// ---------------------------------------------------------------------------
__global__ void mlp_kernel(const int*   __restrict__ users,
                           const int*   __restrict__ items,
                           const float* __restrict__ uemb,
                           const float* __restrict__ iemb,
                           const float* __restrict__ W0,
                           const float* __restrict__ b0,
                           const float* __restrict__ W1,
                           const float* __restrict__ b1,
                           const float* __restrict__ Wa,
                           const float* __restrict__ ba,
                           float* __restrict__ out)
{
    __shared__ float sv[8][128];
    __shared__ float sh0[8][64];

    int w    = threadIdx.x >> 5;
    int lane = threadIdx.x & 31;
    int s    = blockIdx.x * 8 + w;
    if (s >= BATCH) return;

    int u  = users[s];
    int it = items[s];
    int ni = NUM_USERS + it;

    #pragma unroll
    for (int k = lane; k < 64; k += 32) {
        float su = uemb[u * LATENT + k]
                 + g_L1[u * LATENT + k] + g_L2[u * LATENT + k] + g_L3[u * LATENT + k];
        float si = iemb[it * LATENT + k]
                 + g_L1[ni * LATENT + k] + g_L2[ni * LATENT + k] + g_L3[ni * LATENT + k];
        sv[w][k]      = 0.25f * su;
        sv[w][64 + k] = 0.25f * si;
    }
    __syncwarp();

    float a0 = b0[lane];
    float a1 = b0[lane + 32];
    #pragma unroll 8
    for (int k = 0; k < 128; k++) {
        float vk = sv[w][k];
        a0 = fmaf(vk, W0[k * 64 + lane],      a0);
        a1 = fmaf(vk, W0[k * 64 + lane + 32], a1);
    }
    sh0[w][lane]      = fmaxf(a0, 0.f);
    sh0[w][lane + 32] = fmaxf(a1, 0.f);
    __syncwarp();

    float h1 = b1[lane];
    #pragma unroll 8
    for (int k = 0; k < 64; k++)
        h1 = fmaf(sh0[w][k], W1[k * 32 + lane], h1);
    h1 = fmaxf(h1, 0.f);

    float tsum = h1 * Wa[lane];
    #pragma unroll
    for (int off = 16; off > 0; off >>= 1)
        tsum += __shfl_down_sync(0xffffffffu, tsum, off);

    if (lane == 0) {
        float logit = tsum + ba[0];
        out[s] = 1.0f / (1.0f + __expf(-logit));
    }
}

// ---------------------------------------------------------------------------
extern "C" void kernel_launch(void* const* d_in, const int* in_sizes, int n_in,
                              void* d_out, int out_size)
{
    const int*   users = (const int*)  d_in[0];
    const int*   items = (const int*)  d_in[1];
    const int*   rows  = (const int*)  d_in[2];
    const int*   cols  = (const int*)  d_in[3];
    const float* vals  = (const float*)d_in[4];
    const float* uemb  = (const float*)d_in[5];
    const float* iemb  = (const float*)d_in[6];
    const float* W0    = (const float*)d_in[7];
    const float* b0    = (const float*)d_in[8];
    const float* W1    = (const float*)d_in[9];
    const float* b1    = (const float*)d_in[10];
    const float* Wa    = (const float*)d_in[11];
    const float* ba    = (const float*)d_in[12];
    float* out = (float*)d_out;

    const int T = 256;
    int nodeBlocks = (N_NODES + T - 1) / T;            // 586
    int edgeBlocks = (N_EDGES + T - 1) / T;            // 9375
    int spmmBlocks = (N_NODES * 32 + T - 1) / T;       // 18750 (warp per row)

    // --- CSR build (graph identical across layers; rebuilt each call) ---
    zero_counts_kernel<<<nodeBlocks, T>>>();
    hist_kernel<<<edgeBlocks, T>>>(rows);
    scan_kernel<<<1, SCAN_T>>>();
    scatter_kernel<<<edgeBlocks, T>>>(rows, cols, vals);

    // --- 3 propagation layers, atomic-free ---
    spmm_csr<<<spmmBlocks, T>>>(uemb, iemb, 0);
    spmm_csr<<<spmmBlocks, T>>>(uemb, iemb, 1);
    spmm_csr<<<spmmBlocks, T>>>(uemb, iemb, 2);

    // --- scoring head ---
    mlp_kernel<<<BATCH / 8, T>>>(users, items, uemb, iemb,
                                 W0, b0, W1, b1, Wa, ba, out);
}

// round 8
// speedup vs baseline: 1.3080x; 1.3080x over previous
#include <cuda_runtime.h>
#include <math.h>

#define NUM_USERS 100000
#define NUM_ITEMS 50000
#define N_NODES   (NUM_USERS + NUM_ITEMS)   // 150000
#define LATENT    64
#define VEC       16                        // float4 per node row
#define N_EDGES   2400000
#define BATCH     16384
#define NODE_F4   (N_NODES * VEC)           // 2.4M float4
#define EG        8                         // edges per thread group

// ---------------------------------------------------------------------------
// Scratch (device globals: allocation-free, graph-capture safe)
// ---------------------------------------------------------------------------
__device__ float g_L1[N_NODES * LATENT];     // layer outputs (38.4 MB each)
__device__ float g_L2[N_NODES * LATENT];
__device__ float g_L3[N_NODES * LATENT];
__device__ int   g_counts[N_NODES];
__device__ int   g_row_ptr[N_NODES + 1];
__device__ int   g_fill[N_NODES];
__device__ int2  g_ecv[N_EDGES];             // (col, val-bits), row-sorted
__device__ int   g_erow[N_EDGES];            // row id per sorted edge

// ---------------------------------------------------------------------------
// zero the layer buffers (RED destinations) and the histogram
// ---------------------------------------------------------------------------
__global__ void zero3_kernel()
{
    int i = blockIdx.x * blockDim.x + threadIdx.x;
    if (i < NODE_F4) {
        float4 z = make_float4(0.f, 0.f, 0.f, 0.f);
        ((float4*)g_L1)[i] = z;
        ((float4*)g_L2)[i] = z;
        ((float4*)g_L3)[i] = z;
    }
    if (i < N_NODES) g_counts[i] = 0;
}

// histogram of destination rows (4-way ILP, fire-and-forget RED)
__global__ void hist_kernel(const int* __restrict__ rows)
{
    int i = 4 * (blockIdx.x * blockDim.x + threadIdx.x);
    if (i + 3 < N_EDGES) {
        int r0 = rows[i], r1 = rows[i+1], r2 = rows[i+2], r3 = rows[i+3];
        atomicAdd(&g_counts[r0], 1); atomicAdd(&g_counts[r1], 1);
        atomicAdd(&g_counts[r2], 1); atomicAdd(&g_counts[r3], 1);
    } else {
        for (int k = i; k < N_EDGES; k++) atomicAdd(&g_counts[rows[k]], 1);
    }
}

// exclusive scan (single block, serial chunks + block scan)
#define SCAN_T   1024
#define SCAN_CHK ((N_NODES + SCAN_T - 1) / SCAN_T)   // 147
__global__ void scan_kernel()
{
    __shared__ int ssum[SCAN_T];
    int t = threadIdx.x;
    int begin = t * SCAN_CHK;
    int end   = min(begin + SCAN_CHK, N_NODES);

    int s = 0;
    for (int i = begin; i < end; i++) s += g_counts[i];
    ssum[t] = s;
    __syncthreads();

    for (int d = 1; d < SCAN_T; d <<= 1) {
        int v = (t >= d) ? ssum[t - d] : 0;
        __syncthreads();
        ssum[t] += v;
        __syncthreads();
    }

    int run = (t == 0) ? 0 : ssum[t - 1];
    for (int i = begin; i < end; i++) {
        g_row_ptr[i] = run;
        g_fill[i]    = run;
        run += g_counts[i];
    }
    if (t == SCAN_T - 1) g_row_ptr[N_NODES] = ssum[SCAN_T - 1];
}

// scatter (col,val) + row into row-sorted order (4 edges/thread for ILP)
__global__ void scatter_kernel(const int*   __restrict__ rows,
                               const int*   __restrict__ cols,
                               const float* __restrict__ vals)
{
    int i = 4 * (blockIdx.x * blockDim.x + threadIdx.x);
    #pragma unroll
    for (int k = 0; k < 4; k++) {
        int e = i + k;
        if (e < N_EDGES) {
            int r   = rows[e];
            int pos = atomicAdd(&g_fill[r], 1);
            g_ecv[pos]  = make_int2(cols[e], __float_as_int(vals[e]));
            g_erow[pos] = r;
        }
    }
}

// ---------------------------------------------------------------------------
// Segmented SPMM: edge-parallel like the scatter design (16 threads per
// edge-group chunk, massive TLP), but each thread owns EG=8 *row-sorted*
// consecutive edges: all 8 gathers issue up front (ILP=8), and same-row
// products fold into a register accumulator -> ~1 RED per 8 edges instead
// of 8. Worst case (all rows distinct) degenerates to the R4 behavior.
// mode 0: emb -> L1 ; 1: L1 -> L2 ; 2: L2 -> L3
// ---------------------------------------------------------------------------
__global__ void spmm_seg(const float4* __restrict__ uemb,
                         const float4* __restrict__ iemb,
                         int mode)
{
    unsigned int t = blockIdx.x * blockDim.x + threadIdx.x; // < (N_EDGES/EG)*16
    unsigned int g = t >> 4;
    unsigned int c = t & 15u;
    unsigned int e0 = g * EG;

    const float4* __restrict__ xs =
        (mode == 1) ? (const float4*)g_L1 : (const float4*)g_L2;
    float4* y = (mode == 0) ? (float4*)g_L1
              : (mode == 1) ? (float4*)g_L2 : (float4*)g_L3;

    // metadata: 64B of (col,val) + 32B of rows, vectorized, warp-broadcast
    int4 cvp[EG / 2];
    const int4* pe = (const int4*)&g_ecv[e0];
    #pragma unroll
    for (int k = 0; k < EG / 2; k++) cvp[k] = pe[k];
    int4 rw0 = ((const int4*)&g_erow[e0])[0];
    int4 rw1 = ((const int4*)&g_erow[e0])[1];
    int rw[EG] = { rw0.x, rw0.y, rw0.z, rw0.w, rw1.x, rw1.y, rw1.z, rw1.w };
    int   col[EG]; float vv[EG];
    #pragma unroll
    for (int k = 0; k < EG / 2; k++) {
        col[2*k]   = cvp[k].x;  vv[2*k]   = __int_as_float(cvp[k].y);
        col[2*k+1] = cvp[k].z;  vv[2*k+1] = __int_as_float(cvp[k].w);
    }

    // issue all 8 gathers back-to-back
    float4 xv[EG];
    #pragma unroll
    for (int k = 0; k < EG; k++) {
        const float4* xr;
        if (mode == 0)
            xr = (col[k] < NUM_USERS) ? uemb + col[k] * VEC
                                      : iemb + (col[k] - NUM_USERS) * VEC;
        else
            xr = xs + col[k] * VEC;
        xv[k] = xr[c];
    }

    // segmented register reduction over the sorted run
    float4 acc;
    int cur = rw[0];
    acc.x = vv[0] * xv[0].x; acc.y = vv[0] * xv[0].y;
    acc.z = vv[0] * xv[0].z; acc.w = vv[0] * xv[0].w;

    #pragma unroll
    for (int k = 1; k < EG; k++) {
        if (rw[k] == cur) {
            acc.x = fmaf(vv[k], xv[k].x, acc.x);
            acc.y = fmaf(vv[k], xv[k].y, acc.y);
            acc.z = fmaf(vv[k], xv[k].z, acc.z);
            acc.w = fmaf(vv[k], xv[k].w, acc.w);
        } else {
            asm volatile("red.global.add.v4.f32 [%0], {%1, %2, %3, %4};"
                         :: "l"(&y[cur * VEC + c]), "f"(acc.x), "f"(acc.y),
                            "f"(acc.z), "f"(acc.w) : "memory");
            cur = rw[k];
            acc.x = vv[k] * xv[k].x; acc.y = vv[k] * xv[k].y;
            acc.z = vv[k] * xv[k].z; acc.w = vv[k] * xv[k].w;
        }
    }
    asm volatile("red.global.add.v4.f32 [%0], {%1, %2, %3, %4};"
                 :: "l"(&y[cur * VEC + c]), "f"(acc.x), "f"(acc.y),
                    "f"(acc.z), "f"(acc.w) : "memory");
}

// ---------------------------------------------------------------------------
// MLP head: one warp per sample (v = 0.25*(e0+l1+l2+l3) formed on the fly)
// ---------------------------------------------------------------------------
__global__ void mlp_kernel(const int*   __restrict__ users,
                           const int*   __restrict__ items,
                           const float* __restrict__ uemb,
                           const float* __restrict__ iemb,
                           const float* __restrict__ W0,
                           const float* __restrict__ b0,
                           const float* __restrict__ W1,
                           const float* __restrict__ b1,
                           const float* __restrict__ Wa,
                           const float* __restrict__ ba,
                           float* __restrict__ out)
{
    __shared__ float sv[8][128];
    __shared__ float sh0[8][64];

    int w    = threadIdx.x >> 5;
    int lane = threadIdx.x & 31;
    int s    = blockIdx.x * 8 + w;
    if (s >= BATCH) return;

    int u  = users[s];
    int it = items[s];
    int ni = NUM_USERS + it;

    #pragma unroll
    for (int k = lane; k < 64; k += 32) {
        float su = uemb[u * LATENT + k]
                 + g_L1[u * LATENT + k] + g_L2[u * LATENT + k] + g_L3[u * LATENT + k];
        float si = iemb[it * LATENT + k]
                 + g_L1[ni * LATENT + k] + g_L2[ni * LATENT + k] + g_L3[ni * LATENT + k];
        sv[w][k]      = 0.25f * su;
        sv[w][64 + k] = 0.25f * si;
    }
    __syncwarp();

    float a0 = b0[lane];
    float a1 = b0[lane + 32];
    #pragma unroll 8
    for (int k = 0; k < 128; k++) {
        float vk = sv[w][k];
        a0 = fmaf(vk, W0[k * 64 + lane],      a0);
        a1 = fmaf(vk, W0[k * 64 + lane + 32], a1);
    }
    sh0[w][lane]      = fmaxf(a0, 0.f);
    sh0[w][lane + 32] = fmaxf(a1, 0.f);
    __syncwarp();

    float h1 = b1[lane];
    #pragma unroll 8
    for (int k = 0; k < 64; k++)
        h1 = fmaf(sh0[w][k], W1[k * 32 + lane], h1);
    h1 = fmaxf(h1, 0.f);

    float tsum = h1 * Wa[lane];
    #pragma unroll
    for (int off = 16; off > 0; off >>= 1)
        tsum += __shfl_down_sync(0xffffffffu, tsum, off);

    if (lane == 0) {
        float logit = tsum + ba[0];
        out[s] = 1.0f / (1.0f + __expf(-logit));
    }
}

// ---------------------------------------------------------------------------
extern "C" void kernel_launch(void* const* d_in, const int* in_sizes, int n_in,
                              void* d_out, int out_size)
{
    const int*   users = (const int*)  d_in[0];
    const int*   items = (const int*)  d_in[1];
    const int*   rows  = (const int*)  d_in[2];
    const int*   cols  = (const int*)  d_in[3];
    const float* vals  = (const float*)d_in[4];
    const float* uemb  = (const float*)d_in[5];
    const float* iemb  = (const float*)d_in[6];
    const float* W0    = (const float*)d_in[7];
    const float* b0    = (const float*)d_in[8];
    const float* W1    = (const float*)d_in[9];
    const float* b1    = (const float*)d_in[10];
    const float* Wa    = (const float*)d_in[11];
    const float* ba    = (const float*)d_in[12];
    float* out = (float*)d_out;

    const int T = 256;
    int zeroBlocks    = (NODE_F4 + T - 1) / T;                 // 9375
    int histBlocks    = (N_EDGES / 4 + T - 1) / T;             // 2344
    int scatterBlocks = (N_EDGES / 4 + T - 1) / T;             // 2344
    int spmmBlocks    = ((N_EDGES / EG) * 16) / T;             // 18750

    // zero layer buffers + histogram, then CSR build
    zero3_kernel<<<zeroBlocks, T>>>();
    hist_kernel<<<histBlocks, T>>>(rows);
    scan_kernel<<<1, SCAN_T>>>();
    scatter_kernel<<<scatterBlocks, T>>>(rows, cols, vals);

    // 3 propagation layers (segmented-reduction scatter)
    spmm_seg<<<spmmBlocks, T>>>((const float4*)uemb, (const float4*)iemb, 0);
    spmm_seg<<<spmmBlocks, T>>>((const float4*)uemb, (const float4*)iemb, 1);
    spmm_seg<<<spmmBlocks, T>>>((const float4*)uemb, (const float4*)iemb, 2);

    // scoring head
    mlp_kernel<<<BATCH / 8, T>>>(users, items, uemb, iemb,
                                 W0, b0, W1, b1, Wa, ba, out);
}

// round 9
// speedup vs baseline: 2.1997x; 1.6818x over previous
#include <cuda_runtime.h>
#include <math.h>

#define NUM_USERS 100000
#define NUM_ITEMS 50000
#define N_NODES   (NUM_USERS + NUM_ITEMS)   // 150000
#define LATENT    64
#define VEC       16                        // float4 per node row
#define N_EDGES   2400000
#define BATCH     16384
#define NODE_F4   (N_NODES * VEC)           // 2.4M float4
#define EG        4                         // edges per thread group
#define SCAN_B    1024
#define NBLK      ((N_NODES + SCAN_B - 1) / SCAN_B)   // 147

// ---------------------------------------------------------------------------
// Scratch (device globals: allocation-free, graph-capture safe)
// ---------------------------------------------------------------------------
__device__ float g_L1[N_NODES * LATENT];     // layer outputs (38.4 MB each)
__device__ float g_L2[N_NODES * LATENT];
__device__ float g_L3[N_NODES * LATENT];
__device__ int   g_counts[N_NODES];
__device__ int   g_row_ptr[N_NODES + 1];
__device__ int   g_fill[N_NODES];
__device__ int   g_psum[NBLK];               // per-block count sums
__device__ int   g_offs[NBLK];               // exclusive block offsets
__device__ int2  g_ecv[N_EDGES];             // (col, val-bits), row-sorted
__device__ int   g_erow[N_EDGES];            // row id per sorted edge

// ---------------------------------------------------------------------------
// zero the layer buffers (RED destinations) and the histogram
// ---------------------------------------------------------------------------
__global__ void zero3_kernel()
{
    int i = blockIdx.x * blockDim.x + threadIdx.x;
    if (i < NODE_F4) {
        float4 z = make_float4(0.f, 0.f, 0.f, 0.f);
        ((float4*)g_L1)[i] = z;
        ((float4*)g_L2)[i] = z;
        ((float4*)g_L3)[i] = z;
    }
    if (i < N_NODES) g_counts[i] = 0;
}

// histogram of destination rows (8-way ILP, fire-and-forget atomics)
__global__ void hist_kernel(const int* __restrict__ rows)
{
    int i = 8 * (blockIdx.x * blockDim.x + threadIdx.x);
    #pragma unroll
    for (int k = 0; k < 8; k++) {
        int e = i + k;
        if (e < N_EDGES) atomicAdd(&g_counts[rows[e]], 1);
    }
}

// --- scan step A: per-block sums of counts (147 blocks x 1024) ---
__global__ void block_sum_kernel()
{
    __shared__ int sh[SCAN_B];
    int b = blockIdx.x, t = threadIdx.x;
    int i = b * SCAN_B + t;
    sh[t] = (i < N_NODES) ? g_counts[i] : 0;
    __syncthreads();
    for (int d = SCAN_B / 2; d > 0; d >>= 1) {
        if (t < d) sh[t] += sh[t + d];
        __syncthreads();
    }
    if (t == 0) g_psum[b] = sh[0];
}

// --- scan step B: exclusive scan of the 147 block sums (1 tiny block) ---
__global__ void scan_partials_kernel()
{
    __shared__ int sh[256];
    int t = threadIdx.x;
    int v = (t < NBLK) ? g_psum[t] : 0;
    sh[t] = v;
    __syncthreads();
    for (int d = 1; d < 256; d <<= 1) {
        int x = (t >= d) ? sh[t - d] : 0;
        __syncthreads();
        sh[t] += x;
        __syncthreads();
    }
    if (t < NBLK) g_offs[t] = sh[t] - v;
}

// --- scan step C: per-block exclusive scan + global offset -> row_ptr/fill ---
__global__ void scan_block_kernel()
{
    __shared__ int sh[SCAN_B];
    int b = blockIdx.x, t = threadIdx.x;
    int i = b * SCAN_B + t;
    int v = (i < N_NODES) ? g_counts[i] : 0;
    sh[t] = v;
    __syncthreads();
    for (int d = 1; d < SCAN_B; d <<= 1) {
        int x = (t >= d) ? sh[t - d] : 0;
        __syncthreads();
        sh[t] += x;
        __syncthreads();
    }
    if (i < N_NODES) {
        int excl = sh[t] - v + g_offs[b];
        g_row_ptr[i] = excl;
        g_fill[i]    = excl;
    }
    if (i == 0) g_row_ptr[N_NODES] = N_EDGES;
}

// scatter (col,val) + row into row-sorted order (8 edges/thread for ILP)
__global__ void scatter_kernel(const int*   __restrict__ rows,
                               const int*   __restrict__ cols,
                               const float* __restrict__ vals)
{
    int i = 8 * (blockIdx.x * blockDim.x + threadIdx.x);
    #pragma unroll
    for (int k = 0; k < 8; k++) {
        int e = i + k;
        if (e < N_EDGES) {
            int r   = rows[e];
            int pos = atomicAdd(&g_fill[r], 1);
            g_ecv[pos]  = make_int2(cols[e], __float_as_int(vals[e]));
            g_erow[pos] = r;
        }
    }
}

// predicated vector RED: fires only when cur != nxt (end of a row run).
// Single asm block -> ptxas emits @p RED, no branch, no divergence cost.
#define REDV4P(ptr, a, cur, nxt)                                           \
    asm volatile("{\n\t"                                                   \
                 ".reg .pred p;\n\t"                                       \
                 "setp.ne.s32 p, %5, %6;\n\t"                              \
                 "@p red.global.add.v4.f32 [%0], {%1, %2, %3, %4};\n\t"    \
                 "}"                                                       \
                 :: "l"(ptr), "f"((a).x), "f"((a).y), "f"((a).z),          \
                    "f"((a).w), "r"(cur), "r"(nxt) : "memory")

// ---------------------------------------------------------------------------
// Segmented SPMM: edge-parallel (16 threads per edge-group chunk, massive
// TLP). Each thread owns EG=4 row-sorted consecutive edges: all 4 gathers
// issue up front (ILP=4, ~45 regs), same-row products fold in registers via
// selp-reset, and REDs are predicated on run boundaries -> ~2.7x fewer RED
// bytes than the plain scatter, with zero branching.
// mode 0: emb -> L1 ; 1: L1 -> L2 ; 2: L2 -> L3
// ---------------------------------------------------------------------------
__global__ void spmm_seg(const float4* __restrict__ uemb,
                         const float4* __restrict__ iemb,
                         int mode)
{
    unsigned int t = blockIdx.x * blockDim.x + threadIdx.x; // < (N_EDGES/EG)*16
    unsigned int g = t >> 4;
    unsigned int c = t & 15u;
    unsigned int e0 = g * EG;

    const float4* __restrict__ xs =
        (mode == 1) ? (const float4*)g_L1 : (const float4*)g_L2;
    float4* y = (mode == 0) ? (float4*)g_L1
              : (mode == 1) ? (float4*)g_L2 : (float4*)g_L3;

    // metadata: 32B (col,val) + 16B rows, vectorized, broadcast in half-warp
    int4 m0  = ((const int4*)&g_ecv[e0])[0];      // edges 0,1
    int4 m1  = ((const int4*)&g_ecv[e0])[1];      // edges 2,3
    int4 rw4 = *(const int4*)&g_erow[e0];

    int   col[EG] = { m0.x, m0.z, m1.x, m1.z };
    float vv[EG]  = { __int_as_float(m0.y), __int_as_float(m0.w),
                      __int_as_float(m1.y), __int_as_float(m1.w) };
    int   rw[EG]  = { rw4.x, rw4.y, rw4.z, rw4.w };

    // issue all 4 gathers back-to-back
    float4 xv[EG];
    #pragma unroll
    for (int k = 0; k < EG; k++) {
        const float4* xr;
        if (mode == 0)
            xr = (col[k] < NUM_USERS) ? uemb + col[k] * VEC
                                      : iemb + (col[k] - NUM_USERS) * VEC;
        else
            xr = xs + col[k] * VEC;
        xv[k] = xr[c];
    }

    // branch-free segmented reduction
    float4 acc = make_float4(0.f, 0.f, 0.f, 0.f);
    #pragma unroll
    for (int k = 0; k < EG; k++) {
        bool cont = (k > 0) && (rw[k] == rw[k - 1]);
        acc.x = cont ? acc.x : 0.f;
        acc.y = cont ? acc.y : 0.f;
        acc.z = cont ? acc.z : 0.f;
        acc.w = cont ? acc.w : 0.f;
        acc.x = fmaf(vv[k], xv[k].x, acc.x);
        acc.y = fmaf(vv[k], xv[k].y, acc.y);
        acc.z = fmaf(vv[k], xv[k].z, acc.z);
        acc.w = fmaf(vv[k], xv[k].w, acc.w);
        int nxt = (k < EG - 1) ? rw[k + 1] : -1;
        REDV4P(&y[rw[k] * VEC + c], acc, rw[k], nxt);
    }
}

// ---------------------------------------------------------------------------
// MLP head: one warp per sample (v = 0.25*(e0+l1+l2+l3) formed on the fly)
// ---------------------------------------------------------------------------
__global__ void mlp_kernel(const int*   __restrict__ users,
                           const int*   __restrict__ items,
                           const float* __restrict__ uemb,
                           const float* __restrict__ iemb,
                           const float* __restrict__ W0,
                           const float* __restrict__ b0,
                           const float* __restrict__ W1,
                           const float* __restrict__ b1,
                           const float* __restrict__ Wa,
                           const float* __restrict__ ba,
                           float* __restrict__ out)
{
    __shared__ float sv[8][128];
    __shared__ float sh0[8][64];

    int w    = threadIdx.x >> 5;
    int lane = threadIdx.x & 31;
    int s    = blockIdx.x * 8 + w;
    if (s >= BATCH) return;

    int u  = users[s];
    int it = items[s];
    int ni = NUM_USERS + it;

    #pragma unroll
    for (int k = lane; k < 64; k += 32) {
        float su = uemb[u * LATENT + k]
                 + g_L1[u * LATENT + k] + g_L2[u * LATENT + k] + g_L3[u * LATENT + k];
        float si = iemb[it * LATENT + k]
                 + g_L1[ni * LATENT + k] + g_L2[ni * LATENT + k] + g_L3[ni * LATENT + k];
        sv[w][k]      = 0.25f * su;
        sv[w][64 + k] = 0.25f * si;
    }
    __syncwarp();

    float a0 = b0[lane];
    float a1 = b0[lane + 32];
    #pragma unroll 8
    for (int k = 0; k < 128; k++) {
        float vk = sv[w][k];
        a0 = fmaf(vk, W0[k * 64 + lane],      a0);
        a1 = fmaf(vk, W0[k * 64 + lane + 32], a1);
    }
    sh0[w][lane]      = fmaxf(a0, 0.f);
    sh0[w][lane + 32] = fmaxf(a1, 0.f);
    __syncwarp();

    float h1 = b1[lane];
    #pragma unroll 8
    for (int k = 0; k < 64; k++)
        h1 = fmaf(sh0[w][k], W1[k * 32 + lane], h1);
    h1 = fmaxf(h1, 0.f);

    float tsum = h1 * Wa[lane];
    #pragma unroll
    for (int off = 16; off > 0; off >>= 1)
        tsum += __shfl_down_sync(0xffffffffu, tsum, off);

    if (lane == 0) {
        float logit = tsum + ba[0];
        out[s] = 1.0f / (1.0f + __expf(-logit));
    }
}

// ---------------------------------------------------------------------------
extern "C" void kernel_launch(void* const* d_in, const int* in_sizes, int n_in,
                              void* d_out, int out_size)
{
    const int*   users = (const int*)  d_in[0];
    const int*   items = (const int*)  d_in[1];
    const int*   rows  = (const int*)  d_in[2];
    const int*   cols  = (const int*)  d_in[3];
    const float* vals  = (const float*)d_in[4];
    const float* uemb  = (const float*)d_in[5];
    const float* iemb  = (const float*)d_in[6];
    const float* W0    = (const float*)d_in[7];
    const float* b0    = (const float*)d_in[8];
    const float* W1    = (const float*)d_in[9];
    const float* b1    = (const float*)d_in[10];
    const float* Wa    = (const float*)d_in[11];
    const float* ba    = (const float*)d_in[12];
    float* out = (float*)d_out;

    const int T = 256;
    int zeroBlocks = (NODE_F4 + T - 1) / T;                    // 9375
    int e8Blocks   = (N_EDGES / 8 + T - 1) / T;                // 1172
    int spmmBlocks = ((N_EDGES / EG) * 16) / T;                // 37500

    // zero layer buffers + histogram, then CSR build
    zero3_kernel<<<zeroBlocks, T>>>();
    hist_kernel<<<e8Blocks, T>>>(rows);
    block_sum_kernel<<<NBLK, SCAN_B>>>();
    scan_partials_kernel<<<1, 256>>>();
    scan_block_kernel<<<NBLK, SCAN_B>>>();
    scatter_kernel<<<e8Blocks, T>>>(rows, cols, vals);

    // 3 propagation layers (segmented-reduction scatter, branch-free)
    spmm_seg<<<spmmBlocks, T>>>((const float4*)uemb, (const float4*)iemb, 0);
    spmm_seg<<<spmmBlocks, T>>>((const float4*)uemb, (const float4*)iemb, 1);
    spmm_seg<<<spmmBlocks, T>>>((const float4*)uemb, (const float4*)iemb, 2);

    // scoring head
    mlp_kernel<<<BATCH / 8, T>>>(users, items, uemb, iemb,
                                 W0, b0, W1, b1, Wa, ba, out);
}

// round 14
// speedup vs baseline: 2.7037x; 1.2291x over previous
#include <cuda_runtime.h>
#include <cuda_fp16.h>
#include <math.h>

#define NUM_USERS 100000
#define NUM_ITEMS 50000
#define N_NODES   (NUM_USERS + NUM_ITEMS)   // 150000
#define LATENT    64
#define VEC       16                        // float4 per node row
#define N_EDGES   2400000
#define BATCH     16384
#define NODE_F4   (N_NODES * VEC)           // 2.4M float4
#define EG        4                         // edges per thread group
#define SCAN_B    1024
#define NBLK      ((N_NODES + SCAN_B - 1) / SCAN_B)   // 147

// ---------------------------------------------------------------------------
// Scratch (device globals: allocation-free, graph-capture safe)
// ---------------------------------------------------------------------------
__device__ float              g_L1[N_NODES * LATENT];   // fp32 layer outputs
__device__ float              g_L2[N_NODES * LATENT];
__device__ float              g_L3[N_NODES * LATENT];
__device__ __half             g_H[N_NODES * LATENT];    // fp16 gather source
__device__ int                g_counts[N_NODES];
__device__ int                g_fill[N_NODES];
__device__ int                g_psum[NBLK];
__device__ int                g_offs[NBLK];
__device__ unsigned long long g_epk[N_EDGES];  // col(18) | row(18)<<18 | val28<<36

// ---------------------------------------------------------------------------
// zero the fp32 layer buffers + histogram, and build the fp16 copy of the
// input embeddings (mode-0 gather source) in the same pass.
// ---------------------------------------------------------------------------
__global__ void zero3_kernel(const float4* __restrict__ uemb,
                             const float4* __restrict__ iemb)
{
    int i = blockIdx.x * blockDim.x + threadIdx.x;
    if (i < NODE_F4) {
        float4 z = make_float4(0.f, 0.f, 0.f, 0.f);
        ((float4*)g_L1)[i] = z;
        ((float4*)g_L2)[i] = z;
        ((float4*)g_L3)[i] = z;

        const int ucnt = NUM_USERS * VEC;
        float4 v = (i < ucnt) ? uemb[i] : iemb[i - ucnt];
        half2 lo = __floats2half2_rn(v.x, v.y);
        half2 hi = __floats2half2_rn(v.z, v.w);
        union { half2 h; unsigned u; } cl, ch;
        cl.h = lo; ch.h = hi;
        uint2 o; o.x = cl.u; o.y = ch.u;
        ((uint2*)g_H)[i] = o;
    }
    if (i < N_NODES) g_counts[i] = 0;
}

// histogram of destination rows (8-way ILP)
__global__ void hist_kernel(const int* __restrict__ rows)
{
    int i = 8 * (blockIdx.x * blockDim.x + threadIdx.x);
    #pragma unroll
    for (int k = 0; k < 8; k++) {
        int e = i + k;
        if (e < N_EDGES) atomicAdd(&g_counts[rows[e]], 1);
    }
}

// --- scan A: per-block sums ---
__global__ void block_sum_kernel()
{
    __shared__ int sh[SCAN_B];
    int b = blockIdx.x, t = threadIdx.x;
    int i = b * SCAN_B + t;
    sh[t] = (i < N_NODES) ? g_counts[i] : 0;
    __syncthreads();
    for (int d = SCAN_B / 2; d > 0; d >>= 1) {
        if (t < d) sh[t] += sh[t + d];
        __syncthreads();
    }
    if (t == 0) g_psum[b] = sh[0];
}

// --- scan B: exclusive scan of 147 block sums ---
__global__ void scan_partials_kernel()
{
    __shared__ int sh[256];
    int t = threadIdx.x;
    int v = (t < NBLK) ? g_psum[t] : 0;
    sh[t] = v;
    __syncthreads();
    for (int d = 1; d < 256; d <<= 1) {
        int x = (t >= d) ? sh[t - d] : 0;
        __syncthreads();
        sh[t] += x;
        __syncthreads();
    }
    if (t < NBLK) g_offs[t] = sh[t] - v;
}

// --- scan C: per-block exclusive scan + offset -> fill cursors ---
__global__ void scan_block_kernel()
{
    __shared__ int sh[SCAN_B];
    int b = blockIdx.x, t = threadIdx.x;
    int i = b * SCAN_B + t;
    int v = (i < N_NODES) ? g_counts[i] : 0;
    sh[t] = v;
    __syncthreads();
    for (int d = 1; d < SCAN_B; d <<= 1) {
        int x = (t >= d) ? sh[t - d] : 0;
        __syncthreads();
        sh[t] += x;
        __syncthreads();
    }
    if (i < N_NODES) g_fill[i] = sh[t] - v + g_offs[b];
}

// scatter one packed 8B record per edge into row-sorted order (8-way ILP).
// val keeps its top 28 bits (sign+exp+19 mantissa): rel err 2^-20.
__global__ void scatter_kernel(const int*   __restrict__ rows,
                               const int*   __restrict__ cols,
                               const float* __restrict__ vals)
{
    int i = 8 * (blockIdx.x * blockDim.x + threadIdx.x);
    #pragma unroll
    for (int k = 0; k < 8; k++) {
        int e = i + k;
        if (e < N_EDGES) {
            int r   = rows[e];
            int pos = atomicAdd(&g_fill[r], 1);
            unsigned vb = __float_as_uint(vals[e]);
            g_epk[pos] = ((unsigned long long)(vb >> 4) << 36)
                       | ((unsigned long long)(unsigned)r << 18)
                       | (unsigned)cols[e];
        }
    }
}

// ---------------------------------------------------------------------------
// convert fp32 layer output -> fp16 gather source.
// mode 1: L1 -> H ; mode 2: L2 -> H
// ---------------------------------------------------------------------------
__global__ void conv_kernel(int mode)
{
    int i = blockIdx.x * blockDim.x + threadIdx.x;
    if (i >= NODE_F4) return;
    float4 v = (mode == 1) ? ((const float4*)g_L1)[i]
                           : ((const float4*)g_L2)[i];
    half2 lo = __floats2half2_rn(v.x, v.y);
    half2 hi = __floats2half2_rn(v.z, v.w);
    union { half2 h; unsigned u; } cl, ch;
    cl.h = lo; ch.h = hi;
    uint2 o; o.x = cl.u; o.y = ch.u;
    ((uint2*)g_H)[i] = o;
}

// predicated vector RED: fires only at row-run boundaries (no branch).
#define REDV4P(ptr, a, cur, nxt)                                           \
    asm volatile("{\n\t"                                                   \
                 ".reg .pred p;\n\t"                                       \
                 "setp.ne.s32 p, %5, %6;\n\t"                              \
                 "@p red.global.add.v4.f32 [%0], {%1, %2, %3, %4};\n\t"    \
                 "}"                                                       \
                 :: "l"(ptr), "f"((a).x), "f"((a).y), "f"((a).z),          \
                    "f"((a).w), "r"(cur), "r"(nxt) : "memory")

// ---------------------------------------------------------------------------
// Segmented SPMM over the fp16 gather source. Edge-parallel: 16 threads per
// group of EG=4 row-sorted edges. Per thread: 32B of packed metadata
// (broadcast within the group), 4 x 8B fp16 gathers (coalesced 128B per
// group, ILP=4), branch-free register fold, predicated fp32 vector-RED at
// run boundaries. mode selects the destination: 0 -> L1, 1 -> L2, 2 -> L3.
// ---------------------------------------------------------------------------
__global__ void spmm_seg(int mode)
{
    unsigned int t = blockIdx.x * blockDim.x + threadIdx.x; // < (N_EDGES/EG)*16
    unsigned int g = t >> 4;
    unsigned int c = t & 15u;
    unsigned int e0 = g * EG;

    float4* y = (mode == 0) ? (float4*)g_L1
              : (mode == 1) ? (float4*)g_L2 : (float4*)g_L3;

    // 32B of packed edges, vectorized, broadcast within the 16-thread group
    ulonglong2 p01 = ((const ulonglong2*)&g_epk[e0])[0];
    ulonglong2 p23 = ((const ulonglong2*)&g_epk[e0])[1];
    unsigned long long pk[EG] = { p01.x, p01.y, p23.x, p23.y };

    int   col[EG], rw[EG];
    float vv[EG];
    #pragma unroll
    for (int k = 0; k < EG; k++) {
        col[k] = (int)(pk[k] & 0x3FFFFULL);
        rw[k]  = (int)((pk[k] >> 18) & 0x3FFFFULL);
        vv[k]  = __uint_as_float((unsigned)(pk[k] >> 36) << 4);
    }

    // issue all 4 fp16 gathers back-to-back (8B each, 128B per group)
    uint2 hv[EG];
    #pragma unroll
    for (int k = 0; k < EG; k++)
        hv[k] = ((const uint2*)g_H)[col[k] * VEC + c];

    // branch-free segmented reduction (fp32 accumulate)
    float4 acc = make_float4(0.f, 0.f, 0.f, 0.f);
    #pragma unroll
    for (int k = 0; k < EG; k++) {
        union { unsigned u; half2 h; } ulo, uhi;
        ulo.u = hv[k].x; uhi.u = hv[k].y;
        float2 lo = __half22float2(ulo.h);
        float2 hi = __half22float2(uhi.h);
        bool cont = (k > 0) && (rw[k] == rw[k - 1]);
        acc.x = cont ? acc.x : 0.f;
        acc.y = cont ? acc.y : 0.f;
        acc.z = cont ? acc.z : 0.f;
        acc.w = cont ? acc.w : 0.f;
        acc.x = fmaf(vv[k], lo.x, acc.x);
        acc.y = fmaf(vv[k], lo.y, acc.y);
        acc.z = fmaf(vv[k], hi.x, acc.z);
        acc.w = fmaf(vv[k], hi.y, acc.w);
        int nxt = (k < EG - 1) ? rw[k + 1] : -1;
        REDV4P(&y[rw[k] * VEC + c], acc, rw[k], nxt);
    }
}

// ---------------------------------------------------------------------------
// MLP head: one warp per sample (v = 0.25*(e0+l1+l2+l3) formed on the fly,
// all read in fp32)
// ---------------------------------------------------------------------------
__global__ void mlp_kernel(const int*   __restrict__ users,
                           const int*   __restrict__ items,
                           const float* __restrict__ uemb,
                           const float* __restrict__ iemb,
                           const float* __restrict__ W0,
                           const float* __restrict__ b0,
                           const float* __restrict__ W1,
                           const float* __restrict__ b1,
                           const float* __restrict__ Wa,
                           const float* __restrict__ ba,
                           float* __restrict__ out)
{
    __shared__ float sv[8][128];
    __shared__ float sh0[8][64];

    int w    = threadIdx.x >> 5;
    int lane = threadIdx.x & 31;
    int s    = blockIdx.x * 8 + w;
    if (s >= BATCH) return;

    int u  = users[s];
    int it = items[s];
    int ni = NUM_USERS + it;

    #pragma unroll
    for (int k = lane; k < 64; k += 32) {
        float su = uemb[u * LATENT + k]
                 + g_L1[u * LATENT + k] + g_L2[u * LATENT + k] + g_L3[u * LATENT + k];
        float si = iemb[it * LATENT + k]
                 + g_L1[ni * LATENT + k] + g_L2[ni * LATENT + k] + g_L3[ni * LATENT + k];
        sv[w][k]      = 0.25f * su;
        sv[w][64 + k] = 0.25f * si;
    }
    __syncwarp();

    float a0 = b0[lane];
    float a1 = b0[lane + 32];
    #pragma unroll 8
    for (int k = 0; k < 128; k++) {
        float vk = sv[w][k];
        a0 = fmaf(vk, W0[k * 64 + lane],      a0);
        a1 = fmaf(vk, W0[k * 64 + lane + 32], a1);
    }
    sh0[w][lane]      = fmaxf(a0, 0.f);
    sh0[w][lane + 32] = fmaxf(a1, 0.f);
    __syncwarp();

    float h1 = b1[lane];
    #pragma unroll 8
    for (int k = 0; k < 64; k++)
        h1 = fmaf(sh0[w][k], W1[k * 32 + lane], h1);
    h1 = fmaxf(h1, 0.f);

    float tsum = h1 * Wa[lane];
    #pragma unroll
    for (int off = 16; off > 0; off >>= 1)
        tsum += __shfl_down_sync(0xffffffffu, tsum, off);

    if (lane == 0) {
        float logit = tsum + ba[0];
        out[s] = 1.0f / (1.0f + __expf(-logit));
    }
}

// ---------------------------------------------------------------------------
extern "C" void kernel_launch(void* const* d_in, const int* in_sizes, int n_in,
                              void* d_out, int out_size)
{
    const int*   users = (const int*)  d_in[0];
    const int*   items = (const int*)  d_in[1];
    const int*   rows  = (const int*)  d_in[2];
    const int*   cols  = (const int*)  d_in[3];
    const float* vals  = (const float*)d_in[4];
    const float* uemb  = (const float*)d_in[5];
    const float* iemb  = (const float*)d_in[6];
    const float* W0    = (const float*)d_in[7];
    const float* b0    = (const float*)d_in[8];
    const float* W1    = (const float*)d_in[9];
    const float* b1    = (const float*)d_in[10];
    const float* Wa    = (const float*)d_in[11];
    const float* ba    = (const float*)d_in[12];
    float* out = (float*)d_out;

    const int T = 256;
    int zeroBlocks = (NODE_F4 + T - 1) / T;                    // 9375
    int e8Blocks   = (N_EDGES / 8 + T - 1) / T;                // 1172
    int spmmBlocks = ((N_EDGES / EG) * 16) / T;                // 37500

    // zero fp32 layer buffers + histogram + fp16(emb) in one pass, then CSR
    zero3_kernel<<<zeroBlocks, T>>>((const float4*)uemb, (const float4*)iemb);
    hist_kernel<<<e8Blocks, T>>>(rows);
    block_sum_kernel<<<NBLK, SCAN_B>>>();
    scan_partials_kernel<<<1, 256>>>();
    scan_block_kernel<<<NBLK, SCAN_B>>>();
    scatter_kernel<<<e8Blocks, T>>>(rows, cols, vals);

    // 3 propagation layers: fp16 gather source, fp32 RED accumulate
    spmm_seg<<<spmmBlocks, T>>>(0);
    conv_kernel<<<zeroBlocks, T>>>(1);
    spmm_seg<<<spmmBlocks, T>>>(1);
    conv_kernel<<<zeroBlocks, T>>>(2);
    spmm_seg<<<spmmBlocks, T>>>(2);

    // scoring head
    mlp_kernel<<<BATCH / 8, T>>>(users, items, uemb, iemb,
                                 W0, b0, W1, b1, Wa, ba, out);
}

// round 17
// speedup vs baseline: 2.8076x; 1.0384x over previous
#include <cuda_runtime.h>
#include <cuda_fp16.h>
#include <math.h>

#define NUM_USERS 100000
#define NUM_ITEMS 50000
#define N_NODES   (NUM_USERS + NUM_ITEMS)   // 150000
#define LATENT    64
#define VEC       16                        // float4 per fp32 row / uint2 per fp16 row
#define N_EDGES   2400000
#define BATCH     16384
#define NODE_F4   (N_NODES * VEC)           // 2.4M float4
#define EG        8                         // edges folded per thread
#define SCAN_B    1024
#define NBLK      ((N_NODES + SCAN_B - 1) / SCAN_B)   // 147

// ---------------------------------------------------------------------------
// Scratch (device globals: allocation-free, graph-capture safe)
// fp32 layer buffers (RED destinations), fp16 gather source.
// ---------------------------------------------------------------------------
__device__ float              g_L1[N_NODES * LATENT];   // fp32 layer outputs
__device__ float              g_L2[N_NODES * LATENT];
__device__ float              g_L3[N_NODES * LATENT];
__device__ __half             g_H[N_NODES * LATENT];    // fp16 gather source
__device__ int                g_counts[N_NODES];
__device__ int                g_fill[N_NODES];
__device__ int                g_psum[NBLK];
__device__ int                g_offs[NBLK];
__device__ unsigned long long g_epk[N_EDGES];  // col(18) | row(18)<<18 | val28<<36

// ---------------------------------------------------------------------------
// zero the fp32 layer buffers + histogram, and build the fp16 copy of the
// input embeddings (mode-0 gather source) in the same pass.
// ---------------------------------------------------------------------------
__global__ void zero3_kernel(const float4* __restrict__ uemb,
                             const float4* __restrict__ iemb)
{
    int i = blockIdx.x * blockDim.x + threadIdx.x;
    if (i < NODE_F4) {
        float4 z = make_float4(0.f, 0.f, 0.f, 0.f);
        ((float4*)g_L1)[i] = z;
        ((float4*)g_L2)[i] = z;
        ((float4*)g_L3)[i] = z;

        const int ucnt = NUM_USERS * VEC;
        float4 v = (i < ucnt) ? uemb[i] : iemb[i - ucnt];
        half2 lo = __floats2half2_rn(v.x, v.y);
        half2 hi = __floats2half2_rn(v.z, v.w);
        union { half2 h; unsigned u; } cl, ch;
        cl.h = lo; ch.h = hi;
        uint2 o; o.x = cl.u; o.y = ch.u;
        ((uint2*)g_H)[i] = o;
    }
    if (i < N_NODES) g_counts[i] = 0;
}

// histogram of destination rows (8-way ILP)
__global__ void hist_kernel(const int* __restrict__ rows)
{
    int i = 8 * (blockIdx.x * blockDim.x + threadIdx.x);
    #pragma unroll
    for (int k = 0; k < 8; k++) {
        int e = i + k;
        if (e < N_EDGES) atomicAdd(&g_counts[rows[e]], 1);
    }
}

// --- scan A: per-block sums ---
__global__ void block_sum_kernel()
{
    __shared__ int sh[SCAN_B];
    int b = blockIdx.x, t = threadIdx.x;
    int i = b * SCAN_B + t;
    sh[t] = (i < N_NODES) ? g_counts[i] : 0;
    __syncthreads();
    for (int d = SCAN_B / 2; d > 0; d >>= 1) {
        if (t < d) sh[t] += sh[t + d];
        __syncthreads();
    }
    if (t == 0) g_psum[b] = sh[0];
}

// --- scan B: exclusive scan of 147 block sums ---
__global__ void scan_partials_kernel()
{
    __shared__ int sh[256];
    int t = threadIdx.x;
    int v = (t < NBLK) ? g_psum[t] : 0;
    sh[t] = v;
    __syncthreads();
    for (int d = 1; d < 256; d <<= 1) {
        int x = (t >= d) ? sh[t - d] : 0;
        __syncthreads();
        sh[t] += x;
        __syncthreads();
    }
    if (t < NBLK) g_offs[t] = sh[t] - v;
}

// --- scan C: per-block exclusive scan + offset -> fill cursors ---
__global__ void scan_block_kernel()
{
    __shared__ int sh[SCAN_B];
    int b = blockIdx.x, t = threadIdx.x;
    int i = b * SCAN_B + t;
    int v = (i < N_NODES) ? g_counts[i] : 0;
    sh[t] = v;
    __syncthreads();
    for (int d = 1; d < SCAN_B; d <<= 1) {
        int x = (t >= d) ? sh[t - d] : 0;
        __syncthreads();
        sh[t] += x;
        __syncthreads();
    }
    if (i < N_NODES) g_fill[i] = sh[t] - v + g_offs[b];
}

// scatter one packed 8B record per edge into row-sorted order (8-way ILP).
// val keeps its top 28 bits (sign+exp+19 mantissa): rel err 2^-20.
__global__ void scatter_kernel(const int*   __restrict__ rows,
                               const int*   __restrict__ cols,
                               const float* __restrict__ vals)
{
    int i = 8 * (blockIdx.x * blockDim.x + threadIdx.x);
    #pragma unroll
    for (int k = 0; k < 8; k++) {
        int e = i + k;
        if (e < N_EDGES) {
            int r   = rows[e];
            int pos = atomicAdd(&g_fill[r], 1);
            unsigned vb = __float_as_uint(vals[e]);
            g_epk[pos] = ((unsigned long long)(vb >> 4) << 36)
                       | ((unsigned long long)(unsigned)r << 18)
                       | (unsigned)cols[e];
        }
    }
}

// ---------------------------------------------------------------------------
// convert fp32 layer output -> fp16 gather source.
// mode 1: L1 -> H ; mode 2: L2 -> H
// ---------------------------------------------------------------------------
__global__ void conv_kernel(int mode)
{
    int i = blockIdx.x * blockDim.x + threadIdx.x;
    if (i >= NODE_F4) return;
    float4 v = (mode == 1) ? ((const float4*)g_L1)[i]
                           : ((const float4*)g_L2)[i];
    half2 lo = __floats2half2_rn(v.x, v.y);
    half2 hi = __floats2half2_rn(v.z, v.w);
    union { half2 h; unsigned u; } cl, ch;
    cl.h = lo; ch.h = hi;
    uint2 o; o.x = cl.u; o.y = ch.u;
    ((uint2*)g_H)[i] = o;
}

// predicated fp32 vector RED: fires only when cur != nxt (run boundary)
#define REDV4P(ptr, a, cur, nxt)                                           \
    asm volatile("{\n\t"                                                   \
                 ".reg .pred p;\n\t"                                       \
                 "setp.ne.s32 p, %5, %6;\n\t"                              \
                 "@p red.global.add.v4.f32 [%0], {%1, %2, %3, %4};\n\t"    \
                 "}"                                                       \
                 :: "l"(ptr), "f"((a).x), "f"((a).y), "f"((a).z),          \
                    "f"((a).w), "r"(cur), "r"(nxt) : "memory")

#define REDV4(ptr, a)                                                      \
    asm volatile("red.global.add.v4.f32 [%0], {%1, %2, %3, %4};"           \
                 :: "l"(ptr), "f"((a).x), "f"((a).y), "f"((a).z),          \
                    "f"((a).w) : "memory")

// ---------------------------------------------------------------------------
// Segmented SPMM over the fp16 gather source, EG=8 folding.
// Edge-parallel: 16 threads per group of 8 row-sorted edges. Per thread:
// 64B packed metadata (broadcast within the group), 8 x 8B fp16 gathers
// (coalesced 128B per group, ILP=8), branch-free fp32 register fold,
// predicated fp32 vector-RED at run boundaries (~1.4 REDs per 8 edges at
// mean degree 16, vs 8 in a plain scatter).
// mode: 0 -> L1, 1 -> L2, 2 -> L3 (source is always g_H)
// ---------------------------------------------------------------------------
__global__ void __launch_bounds__(256) spmm_seg(int mode)
{
    unsigned int t = blockIdx.x * blockDim.x + threadIdx.x; // < (N_EDGES/EG)*16
    unsigned int g = t >> 4;
    unsigned int c = t & 15u;
    unsigned int e0 = g * EG;

    float4* y = (mode == 0) ? (float4*)g_L1
              : (mode == 1) ? (float4*)g_L2 : (float4*)g_L3;

    // 64B of packed edges (4 x 16B), broadcast within the 16-thread group
    ulonglong2 m0 = ((const ulonglong2*)&g_epk[e0])[0];
    ulonglong2 m1 = ((const ulonglong2*)&g_epk[e0])[1];
    ulonglong2 m2 = ((const ulonglong2*)&g_epk[e0])[2];
    ulonglong2 m3 = ((const ulonglong2*)&g_epk[e0])[3];
    unsigned long long pk[EG] = { m0.x, m0.y, m1.x, m1.y,
                                  m2.x, m2.y, m3.x, m3.y };

    int   col[EG], rw[EG];
    float vv[EG];
    #pragma unroll
    for (int k = 0; k < EG; k++) {
        col[k] = (int)(pk[k] & 0x3FFFFULL);
        rw[k]  = (int)((pk[k] >> 18) & 0x3FFFFULL);
        vv[k]  = __uint_as_float((unsigned)(pk[k] >> 36) << 4);
    }

    // issue all 8 fp16 gathers back-to-back (8B each, 128B per group)
    uint2 hv[EG];
    #pragma unroll
    for (int k = 0; k < EG; k++)
        hv[k] = ((const uint2*)g_H)[col[k] * VEC + c];

    // branch-free segmented reduction (fp32 accumulate, fp32 RED)
    float4 acc = make_float4(0.f, 0.f, 0.f, 0.f);
    #pragma unroll
    for (int k = 0; k < EG; k++) {
        union { unsigned u; half2 h; } ulo, uhi;
        ulo.u = hv[k].x; uhi.u = hv[k].y;
        float2 lo = __half22float2(ulo.h);
        float2 hi = __half22float2(uhi.h);
        bool cont = (k > 0) && (rw[k] == rw[k - 1]);
        acc.x = cont ? acc.x : 0.f;
        acc.y = cont ? acc.y : 0.f;
        acc.z = cont ? acc.z : 0.f;
        acc.w = cont ? acc.w : 0.f;
        acc.x = fmaf(vv[k], lo.x, acc.x);
        acc.y = fmaf(vv[k], lo.y, acc.y);
        acc.z = fmaf(vv[k], hi.x, acc.z);
        acc.w = fmaf(vv[k], hi.y, acc.w);
        if (k < EG - 1) {
            REDV4P(&y[rw[k] * VEC + c], acc, rw[k], rw[k + 1]);
        } else {
            REDV4(&y[rw[k] * VEC + c], acc);
        }
    }
}

// ---------------------------------------------------------------------------
// MLP head: one warp per sample (v = 0.25*(e0+l1+l2+l3) formed on the fly,
// all read in fp32)
// ---------------------------------------------------------------------------
__global__ void mlp_kernel(const int*   __restrict__ users,
                           const int*   __restrict__ items,
                           const float* __restrict__ uemb,
                           const float* __restrict__ iemb,
                           const float* __restrict__ W0,
                           const float* __restrict__ b0,
                           const float* __restrict__ W1,
                           const float* __restrict__ b1,
                           const float* __restrict__ Wa,
                           const float* __restrict__ ba,
                           float* __restrict__ out)
{
    __shared__ float sv[8][128];
    __shared__ float sh0[8][64];

    int w    = threadIdx.x >> 5;
    int lane = threadIdx.x & 31;
    int s    = blockIdx.x * 8 + w;
    if (s >= BATCH) return;

    int u  = users[s];
    int it = items[s];
    int ni = NUM_USERS + it;

    #pragma unroll
    for (int k = lane; k < 64; k += 32) {
        float su = uemb[u * LATENT + k]
                 + g_L1[u * LATENT + k] + g_L2[u * LATENT + k] + g_L3[u * LATENT + k];
        float si = iemb[it * LATENT + k]
                 + g_L1[ni * LATENT + k] + g_L2[ni * LATENT + k] + g_L3[ni * LATENT + k];
        sv[w][k]      = 0.25f * su;
        sv[w][64 + k] = 0.25f * si;
    }
    __syncwarp();

    float a0 = b0[lane];
    float a1 = b0[lane + 32];
    #pragma unroll 8
    for (int k = 0; k < 128; k++) {
        float vk = sv[w][k];
        a0 = fmaf(vk, W0[k * 64 + lane],      a0);
        a1 = fmaf(vk, W0[k * 64 + lane + 32], a1);
    }
    sh0[w][lane]      = fmaxf(a0, 0.f);
    sh0[w][lane + 32] = fmaxf(a1, 0.f);
    __syncwarp();

    float h1 = b1[lane];
    #pragma unroll 8
    for (int k = 0; k < 64; k++)
        h1 = fmaf(sh0[w][k], W1[k * 32 + lane], h1);
    h1 = fmaxf(h1, 0.f);

    float tsum = h1 * Wa[lane];
    #pragma unroll
    for (int off = 16; off > 0; off >>= 1)
        tsum += __shfl_down_sync(0xffffffffu, tsum, off);

    if (lane == 0) {
        float logit = tsum + ba[0];
        out[s] = 1.0f / (1.0f + __expf(-logit));
    }
}

// ---------------------------------------------------------------------------
extern "C" void kernel_launch(void* const* d_in, const int* in_sizes, int n_in,
                              void* d_out, int out_size)
{
    const int*   users = (const int*)  d_in[0];
    const int*   items = (const int*)  d_in[1];
    const int*   rows  = (const int*)  d_in[2];
    const int*   cols  = (const int*)  d_in[3];
    const float* vals  = (const float*)d_in[4];
    const float* uemb  = (const float*)d_in[5];
    const float* iemb  = (const float*)d_in[6];
    const float* W0    = (const float*)d_in[7];
    const float* b0    = (const float*)d_in[8];
    const float* W1    = (const float*)d_in[9];
    const float* b1    = (const float*)d_in[10];
    const float* Wa    = (const float*)d_in[11];
    const float* ba    = (const float*)d_in[12];
    float* out = (float*)d_out;

    const int T = 256;
    int zeroBlocks = (NODE_F4 + T - 1) / T;                    // 9375
    int e8Blocks   = (N_EDGES / 8 + T - 1) / T;                // 1172
    int spmmBlocks = ((N_EDGES / EG) * 16) / T;                // 18750

    // zero fp32 layer buffers + histogram + fp16(emb) in one pass, then CSR
    zero3_kernel<<<zeroBlocks, T>>>((const float4*)uemb, (const float4*)iemb);
    hist_kernel<<<e8Blocks, T>>>(rows);
    block_sum_kernel<<<NBLK, SCAN_B>>>();
    scan_partials_kernel<<<1, 256>>>();
    scan_block_kernel<<<NBLK, SCAN_B>>>();
    scatter_kernel<<<e8Blocks, T>>>(rows, cols, vals);

    // 3 propagation layers: fp16 gather source, fp32 RED accumulate, EG=8
    spmm_seg<<<spmmBlocks, T>>>(0);
    conv_kernel<<<zeroBlocks, T>>>(1);
    spmm_seg<<<spmmBlocks, T>>>(1);
    conv_kernel<<<zeroBlocks, T>>>(2);
    spmm_seg<<<spmmBlocks, T>>>(2);

    // scoring head
    mlp_kernel<<<BATCH / 8, T>>>(users, items, uemb, iemb,
                                 W0, b0, W1, b1, Wa, ba, out);
}